// round 1
// baseline (speedup 1.0000x reference)
#include <cuda_runtime.h>
#include <math.h>
#include <stdint.h>

#define IN_DIM 128
#define OUTD   64
#define MAXN   100000
#define MAXE   1600000

// ---- device scratch (no allocations allowed) ----
__device__ float g_z[MAXN * OUTD];    // z = h @ W_fc
__device__ float g_u[MAXN * OUTD];    // u = z @ W_edge[:64]
__device__ float g_v[MAXN * OUTD];    // v = z @ W_edge[64:]
__device__ float g_as[MAXN];          // a_s = z . W_attn[:64]
__device__ float g_M[MAXN];           // segment max of a_s[src]
__device__ float g_den[MAXN];         // segment sum of exp(a_s[src]-M)
__device__ int   g_deg[MAXN];         // in-degree

// ------------------------------------------------------------------
// K0: init scratch + zero output
__global__ void k_init(float* __restrict__ out, int n) {
    int i = blockIdx.x * blockDim.x + threadIdx.x;
    if (i < n) {
        g_M[i]   = __int_as_float(0xff800000); // -inf
        g_den[i] = 0.0f;
        g_deg[i] = 0;
    }
    if (i < n * OUTD) out[i] = 0.0f;
}

// ------------------------------------------------------------------
// K1a: z = h @ W_fc   ([n,128] @ [128,64])
// 256 threads, 16 nodes per block. j = tid&63 output column,
// ty = tid>>6 selects a group of 4 nodes.
__global__ __launch_bounds__(256) void k_proj(const float* __restrict__ h,
                                              const float* __restrict__ Wfc,
                                              int n) {
    __shared__ float sW[IN_DIM * OUTD];   // 32 KB
    __shared__ float sH[16][IN_DIM];      // 8 KB
    int tid = threadIdx.x;
    int j = tid & 63;
    int ty = tid >> 6;
    int nbase = blockIdx.x * 16;

    for (int i = tid; i < IN_DIM * OUTD / 4; i += 256)
        ((float4*)sW)[i] = ((const float4*)Wfc)[i];

    for (int i = tid; i < 16 * IN_DIM / 4; i += 256) {
        int nl = i >> 5;      // 32 float4 per 128-float row
        int kk = i & 31;
        int nn = nbase + nl;
        float4 val = (nn < n) ? ((const float4*)h)[(size_t)nn * 32 + kk]
                              : make_float4(0.f, 0.f, 0.f, 0.f);
        ((float4*)&sH[nl][0])[kk] = val;
    }
    __syncthreads();

    float acc0 = 0.f, acc1 = 0.f, acc2 = 0.f, acc3 = 0.f;
    int nb = ty * 4;
    #pragma unroll 8
    for (int k = 0; k < IN_DIM; k++) {
        float wv = sW[k * OUTD + j];
        acc0 = fmaf(sH[nb + 0][k], wv, acc0);
        acc1 = fmaf(sH[nb + 1][k], wv, acc1);
        acc2 = fmaf(sH[nb + 2][k], wv, acc2);
        acc3 = fmaf(sH[nb + 3][k], wv, acc3);
    }
    int nn = nbase + nb;
    if (nn + 0 < n) g_z[(nn + 0) * OUTD + j] = acc0;
    if (nn + 1 < n) g_z[(nn + 1) * OUTD + j] = acc1;
    if (nn + 2 < n) g_z[(nn + 2) * OUTD + j] = acc2;
    if (nn + 3 < n) g_z[(nn + 3) * OUTD + j] = acc3;
}

// ------------------------------------------------------------------
// K1b: u = z @ W_edge[:64], v = z @ W_edge[64:], a_s = z . W_attn[:64]
__global__ __launch_bounds__(256) void k_uva(const float* __restrict__ Wattn,
                                             const float* __restrict__ Wedge,
                                             int n) {
    __shared__ float sW1[OUTD * OUTD];   // 16 KB
    __shared__ float sW2[OUTD * OUTD];   // 16 KB
    __shared__ float sZ[16][OUTD];       // 4 KB
    __shared__ float sWa[OUTD];
    int tid = threadIdx.x;
    int j = tid & 63;
    int ty = tid >> 6;
    int nbase = blockIdx.x * 16;

    for (int i = tid; i < OUTD * OUTD / 4; i += 256) {
        ((float4*)sW1)[i] = ((const float4*)Wedge)[i];
        ((float4*)sW2)[i] = ((const float4*)(Wedge + OUTD * OUTD))[i];
    }
    if (tid < OUTD) sWa[tid] = Wattn[tid];

    for (int i = tid; i < 16 * OUTD / 4; i += 256) {
        int nl = i >> 4;      // 16 float4 per 64-float row
        int kk = i & 15;
        int nn = nbase + nl;
        float4 val = (nn < n) ? ((const float4*)g_z)[(size_t)nn * 16 + kk]
                              : make_float4(0.f, 0.f, 0.f, 0.f);
        ((float4*)&sZ[nl][0])[kk] = val;
    }
    __syncthreads();

    float ua0 = 0.f, ua1 = 0.f, ua2 = 0.f, ua3 = 0.f;
    float va0 = 0.f, va1 = 0.f, va2 = 0.f, va3 = 0.f;
    int nb = ty * 4;
    #pragma unroll 8
    for (int k = 0; k < OUTD; k++) {
        float w1 = sW1[k * OUTD + j];
        float w2 = sW2[k * OUTD + j];
        float z0 = sZ[nb + 0][k], z1 = sZ[nb + 1][k];
        float z2 = sZ[nb + 2][k], z3 = sZ[nb + 3][k];
        ua0 = fmaf(z0, w1, ua0); va0 = fmaf(z0, w2, va0);
        ua1 = fmaf(z1, w1, ua1); va1 = fmaf(z1, w2, va1);
        ua2 = fmaf(z2, w1, ua2); va2 = fmaf(z2, w2, va2);
        ua3 = fmaf(z3, w1, ua3); va3 = fmaf(z3, w2, va3);
    }
    int nn = nbase + nb;
    if (nn + 0 < n) { g_u[(nn + 0) * OUTD + j] = ua0; g_v[(nn + 0) * OUTD + j] = va0; }
    if (nn + 1 < n) { g_u[(nn + 1) * OUTD + j] = ua1; g_v[(nn + 1) * OUTD + j] = va1; }
    if (nn + 2 < n) { g_u[(nn + 2) * OUTD + j] = ua2; g_v[(nn + 2) * OUTD + j] = va2; }
    if (nn + 3 < n) { g_u[(nn + 3) * OUTD + j] = ua3; g_v[(nn + 3) * OUTD + j] = va3; }

    if (tid < 16) {
        int nn2 = nbase + tid;
        if (nn2 < n) {
            float a = 0.f;
            #pragma unroll 8
            for (int k = 0; k < OUTD; k++) a = fmaf(sZ[tid][k], sWa[k], a);
            g_as[nn2] = a;
        }
    }
}

// ------------------------------------------------------------------
// K2: segment max of a_s[src] over dst, plus in-degree
__global__ void k_max(const int* __restrict__ src, const int* __restrict__ dst, int e) {
    int i = blockIdx.x * blockDim.x + threadIdx.x;
    if (i >= e) return;
    int s = src[i], d = dst[i];
    float v = g_as[s];
    if (v >= 0.f) atomicMax((int*)&g_M[d], __float_as_int(v));
    else          atomicMin((unsigned int*)&g_M[d], __float_as_uint(v));
    atomicAdd(&g_deg[d], 1);
}

// ------------------------------------------------------------------
// K3: denom = segment sum of exp(a_s[src] - M[dst])
__global__ void k_den(const int* __restrict__ src, const int* __restrict__ dst, int e) {
    int i = blockIdx.x * blockDim.x + threadIdx.x;
    if (i >= e) return;
    float w = __expf(g_as[src[i]] - g_M[dst[i]]);
    atomicAdd(&g_den[dst[i]], w);
}

// ------------------------------------------------------------------
// K4: scatter  out[d] += alpha * z[s] + u[s]   (16 threads per edge, 4 cols each)
__global__ __launch_bounds__(256) void k_scatter(const int* __restrict__ src,
                                                 const int* __restrict__ dst,
                                                 float* __restrict__ out, int e) {
    long long tid = (long long)blockIdx.x * blockDim.x + threadIdx.x;
    int i = (int)(tid >> 4);
    if (i >= e) return;
    int g = (int)(tid & 15);
    int s = src[i], d = dst[i];
    float alpha = __expf(g_as[s] - g_M[d]) / g_den[d];
    float4 z4 = ((const float4*)g_z)[(size_t)s * 16 + g];
    float4 u4 = ((const float4*)g_u)[(size_t)s * 16 + g];
    float* p = out + (size_t)d * OUTD + g * 4;
    atomicAdd(p + 0, fmaf(alpha, z4.x, u4.x));
    atomicAdd(p + 1, fmaf(alpha, z4.y, u4.y));
    atomicAdd(p + 2, fmaf(alpha, z4.z, u4.z));
    atomicAdd(p + 3, fmaf(alpha, z4.w, u4.w));
}

// ------------------------------------------------------------------
// K5: out += deg[n] * v[n]
__global__ void k_final(float* __restrict__ out, int n) {
    int i = blockIdx.x * blockDim.x + threadIdx.x;
    if (i >= n * OUTD) return;
    int nn = i >> 6;
    out[i] += (float)g_deg[nn] * g_v[i];
}

// ------------------------------------------------------------------
extern "C" void kernel_launch(void* const* d_in, const int* in_sizes, int n_in,
                              void* d_out, int out_size) {
    const float* h     = (const float*)d_in[0];
    const float* W_fc  = (const float*)d_in[1];
    const float* W_attn= (const float*)d_in[2];
    const float* W_edge= (const float*)d_in[3];
    const int*   src   = (const int*)d_in[4];
    const int*   dst   = (const int*)d_in[5];
    float* out = (float*)d_out;

    int n = in_sizes[0] / IN_DIM;   // 100000
    int e = in_sizes[4];            // 1600000

    k_init<<<(n * OUTD + 255) / 256, 256>>>(out, n);
    k_proj<<<(n + 15) / 16, 256>>>(h, W_fc, n);
    k_uva<<<(n + 15) / 16, 256>>>(W_attn, W_edge, n);
    k_max<<<(e + 255) / 256, 256>>>(src, dst, e);
    k_den<<<(e + 255) / 256, 256>>>(src, dst, e);
    long long sthreads = (long long)e * 16;
    k_scatter<<<(unsigned)((sthreads + 255) / 256), 256>>>(src, dst, out, e);
    k_final<<<(n * OUTD + 255) / 256, 256>>>(out, n);
}

// round 2
// speedup vs baseline: 1.2200x; 1.2200x over previous
#include <cuda_runtime.h>
#include <math.h>
#include <stdint.h>

#define IN_DIM 128
#define OUTD   64
#define MAXN   100000
#define MAXE   1600000

// ---- device scratch (no allocations allowed) ----
__device__ float g_z[MAXN * OUTD];    // z = h @ W_fc
__device__ float g_u[MAXN * OUTD];    // u = z @ W_edge[:64]
__device__ float g_v[MAXN * OUTD];    // v = z @ W_edge[64:]
__device__ float g_as[MAXN];          // a_s = z . W_attn[:64]
__device__ float g_M[MAXN];           // segment max of a_s[src]
__device__ int   g_deg[MAXN];         // in-degree
__device__ int   g_off[MAXN + 1];     // exclusive prefix of deg
__device__ int   g_cur[MAXN];         // bucket cursors
__device__ int   g_esrc[MAXE];        // dst-sorted src indices
__device__ float g_w[MAXE];           // dst-sorted edge weights exp(a_s - M)

// ------------------------------------------------------------------
// K0: init scratch
__global__ void k_init(int n) {
    int i = blockIdx.x * blockDim.x + threadIdx.x;
    if (i < n) {
        g_M[i]   = __int_as_float(0xff800000); // -inf
        g_deg[i] = 0;
        g_cur[i] = 0;
    }
}

// ------------------------------------------------------------------
// K1a: z = h @ W_fc   ([n,128] @ [128,64])
__global__ __launch_bounds__(256) void k_proj(const float* __restrict__ h,
                                              const float* __restrict__ Wfc,
                                              int n) {
    __shared__ float sW[IN_DIM * OUTD];   // 32 KB
    __shared__ float sH[16][IN_DIM];      // 8 KB
    int tid = threadIdx.x;
    int j = tid & 63;
    int ty = tid >> 6;
    int nbase = blockIdx.x * 16;

    for (int i = tid; i < IN_DIM * OUTD / 4; i += 256)
        ((float4*)sW)[i] = ((const float4*)Wfc)[i];

    for (int i = tid; i < 16 * IN_DIM / 4; i += 256) {
        int nl = i >> 5;
        int kk = i & 31;
        int nn = nbase + nl;
        float4 val = (nn < n) ? ((const float4*)h)[(size_t)nn * 32 + kk]
                              : make_float4(0.f, 0.f, 0.f, 0.f);
        ((float4*)&sH[nl][0])[kk] = val;
    }
    __syncthreads();

    float acc0 = 0.f, acc1 = 0.f, acc2 = 0.f, acc3 = 0.f;
    int nb = ty * 4;
    #pragma unroll 8
    for (int k = 0; k < IN_DIM; k++) {
        float wv = sW[k * OUTD + j];
        acc0 = fmaf(sH[nb + 0][k], wv, acc0);
        acc1 = fmaf(sH[nb + 1][k], wv, acc1);
        acc2 = fmaf(sH[nb + 2][k], wv, acc2);
        acc3 = fmaf(sH[nb + 3][k], wv, acc3);
    }
    int nn = nbase + nb;
    if (nn + 0 < n) g_z[(nn + 0) * OUTD + j] = acc0;
    if (nn + 1 < n) g_z[(nn + 1) * OUTD + j] = acc1;
    if (nn + 2 < n) g_z[(nn + 2) * OUTD + j] = acc2;
    if (nn + 3 < n) g_z[(nn + 3) * OUTD + j] = acc3;
}

// ------------------------------------------------------------------
// K1b: u = z @ W_edge[:64], v = z @ W_edge[64:], a_s = z . W_attn[:64]
__global__ __launch_bounds__(256) void k_uva(const float* __restrict__ Wattn,
                                             const float* __restrict__ Wedge,
                                             int n) {
    __shared__ float sW1[OUTD * OUTD];
    __shared__ float sW2[OUTD * OUTD];
    __shared__ float sZ[16][OUTD];
    __shared__ float sWa[OUTD];
    int tid = threadIdx.x;
    int j = tid & 63;
    int ty = tid >> 6;
    int nbase = blockIdx.x * 16;

    for (int i = tid; i < OUTD * OUTD / 4; i += 256) {
        ((float4*)sW1)[i] = ((const float4*)Wedge)[i];
        ((float4*)sW2)[i] = ((const float4*)(Wedge + OUTD * OUTD))[i];
    }
    if (tid < OUTD) sWa[tid] = Wattn[tid];

    for (int i = tid; i < 16 * OUTD / 4; i += 256) {
        int nl = i >> 4;
        int kk = i & 15;
        int nn = nbase + nl;
        float4 val = (nn < n) ? ((const float4*)g_z)[(size_t)nn * 16 + kk]
                              : make_float4(0.f, 0.f, 0.f, 0.f);
        ((float4*)&sZ[nl][0])[kk] = val;
    }
    __syncthreads();

    float ua0 = 0.f, ua1 = 0.f, ua2 = 0.f, ua3 = 0.f;
    float va0 = 0.f, va1 = 0.f, va2 = 0.f, va3 = 0.f;
    int nb = ty * 4;
    #pragma unroll 8
    for (int k = 0; k < OUTD; k++) {
        float w1 = sW1[k * OUTD + j];
        float w2 = sW2[k * OUTD + j];
        float z0 = sZ[nb + 0][k], z1 = sZ[nb + 1][k];
        float z2 = sZ[nb + 2][k], z3 = sZ[nb + 3][k];
        ua0 = fmaf(z0, w1, ua0); va0 = fmaf(z0, w2, va0);
        ua1 = fmaf(z1, w1, ua1); va1 = fmaf(z1, w2, va1);
        ua2 = fmaf(z2, w1, ua2); va2 = fmaf(z2, w2, va2);
        ua3 = fmaf(z3, w1, ua3); va3 = fmaf(z3, w2, va3);
    }
    int nn = nbase + nb;
    if (nn + 0 < n) { g_u[(nn + 0) * OUTD + j] = ua0; g_v[(nn + 0) * OUTD + j] = va0; }
    if (nn + 1 < n) { g_u[(nn + 1) * OUTD + j] = ua1; g_v[(nn + 1) * OUTD + j] = va1; }
    if (nn + 2 < n) { g_u[(nn + 2) * OUTD + j] = ua2; g_v[(nn + 2) * OUTD + j] = va2; }
    if (nn + 3 < n) { g_u[(nn + 3) * OUTD + j] = ua3; g_v[(nn + 3) * OUTD + j] = va3; }

    if (tid < 16) {
        int nn2 = nbase + tid;
        if (nn2 < n) {
            float a = 0.f;
            #pragma unroll 8
            for (int k = 0; k < OUTD; k++) a = fmaf(sZ[tid][k], sWa[k], a);
            g_as[nn2] = a;
        }
    }
}

// ------------------------------------------------------------------
// K2: segment max of a_s[src] over dst, plus in-degree
__global__ void k_max(const int* __restrict__ src, const int* __restrict__ dst, int e) {
    int i = blockIdx.x * blockDim.x + threadIdx.x;
    if (i >= e) return;
    int s = src[i], d = dst[i];
    float v = g_as[s];
    if (v >= 0.f) atomicMax((int*)&g_M[d], __float_as_int(v));
    else          atomicMin((unsigned int*)&g_M[d], __float_as_uint(v));
    atomicAdd(&g_deg[d], 1);
}

// ------------------------------------------------------------------
// K_scan: exclusive prefix sum of g_deg into g_off (single block, 1024 thr)
__global__ __launch_bounds__(1024) void k_scan(int n) {
    __shared__ int warpsum[32];
    __shared__ int chunk_total;
    int tid = threadIdx.x, lane = tid & 31, wid = tid >> 5;
    int running = 0;
    for (int base = 0; base < n; base += 1024) {
        int i = base + tid;
        int v = (i < n) ? g_deg[i] : 0;
        int x = v;
        #pragma unroll
        for (int o = 1; o < 32; o <<= 1) {
            int t = __shfl_up_sync(0xffffffffu, x, o);
            if (lane >= o) x += t;
        }
        if (lane == 31) warpsum[wid] = x;
        __syncthreads();
        if (wid == 0) {
            int s = warpsum[lane];
            #pragma unroll
            for (int o = 1; o < 32; o <<= 1) {
                int t = __shfl_up_sync(0xffffffffu, s, o);
                if (lane >= o) s += t;
            }
            warpsum[lane] = s;
            if (lane == 31) chunk_total = s;
        }
        __syncthreads();
        int wofs = (wid > 0) ? warpsum[wid - 1] : 0;
        int incl = x + wofs;
        if (i < n) g_off[i] = running + incl - v;
        running += chunk_total;
        __syncthreads();
    }
    if (tid == 0) g_off[n] = running;
}

// ------------------------------------------------------------------
// K_bucket: counting-sort edges by dst; store src idx + weight
__global__ void k_bucket(const int* __restrict__ src, const int* __restrict__ dst, int e) {
    int i = blockIdx.x * blockDim.x + threadIdx.x;
    if (i >= e) return;
    int s = src[i], d = dst[i];
    int pos = g_off[d] + atomicAdd(&g_cur[d], 1);
    g_esrc[pos] = s;
    g_w[pos] = __expf(g_as[s] - g_M[d]);
}

// ------------------------------------------------------------------
// K_accum: per-node segmented reduction, no atomics.
// 64 threads per node (one per output column), 4 nodes per block.
__global__ __launch_bounds__(256) void k_accum(float* __restrict__ out, int n) {
    int node = blockIdx.x * 4 + (threadIdx.x >> 6);
    int j = threadIdx.x & 63;
    if (node >= n) return;
    int off0 = g_off[node], off1 = g_off[node + 1];
    float den = 0.f, az = 0.f, au = 0.f;
    #pragma unroll 4
    for (int e = off0; e < off1; e++) {
        int s = g_esrc[e];          // broadcast across 64 threads
        float w = g_w[e];           // broadcast
        den += w;
        az = fmaf(w, g_z[(size_t)s * OUTD + j], az);
        au += g_u[(size_t)s * OUTD + j];
    }
    float r = (den > 0.f) ? az / den : 0.f;
    r += au + (float)(off1 - off0) * g_v[(size_t)node * OUTD + j];
    out[(size_t)node * OUTD + j] = r;
}

// ------------------------------------------------------------------
extern "C" void kernel_launch(void* const* d_in, const int* in_sizes, int n_in,
                              void* d_out, int out_size) {
    const float* h      = (const float*)d_in[0];
    const float* W_fc   = (const float*)d_in[1];
    const float* W_attn = (const float*)d_in[2];
    const float* W_edge = (const float*)d_in[3];
    const int*   src    = (const int*)d_in[4];
    const int*   dst    = (const int*)d_in[5];
    float* out = (float*)d_out;

    int n = in_sizes[0] / IN_DIM;   // 100000
    int e = in_sizes[4];            // 1600000

    k_init  <<<(n + 255) / 256, 256>>>(n);
    k_proj  <<<(n + 15) / 16, 256>>>(h, W_fc, n);
    k_uva   <<<(n + 15) / 16, 256>>>(W_attn, W_edge, n);
    k_max   <<<(e + 255) / 256, 256>>>(src, dst, e);
    k_scan  <<<1, 1024>>>(n);
    k_bucket<<<(e + 255) / 256, 256>>>(src, dst, e);
    k_accum <<<(n + 3) / 4, 256>>>(out, n);
}

// round 3
// speedup vs baseline: 1.3198x; 1.0818x over previous
#include <cuda_runtime.h>
#include <math.h>
#include <stdint.h>

#define IN_DIM 128
#define OUTD   64
#define MAXN   100000
#define MAXE   1600000
#define SCANB  1024

// ---- device scratch ----
__device__ float g_z[MAXN * OUTD];    // z = h @ W_fc
__device__ float g_as[MAXN];          // a_s = z . W_attn[:64]
__device__ int   g_deg[MAXN];         // in-degree
__device__ int   g_off[MAXN + 1];     // exclusive prefix of deg
__device__ int   g_cur[MAXN];         // bucket cursors
__device__ int2  g_ew[MAXE];          // dst-sorted (src, bits(w))
__device__ int   g_bsum[(MAXN + SCANB - 1) / SCANB];

// ------------------------------------------------------------------
__global__ void k_init(int n) {
    int i = blockIdx.x * blockDim.x + threadIdx.x;
    if (i < n) { g_deg[i] = 0; g_cur[i] = 0; }
}

// ------------------------------------------------------------------
// K1: z = h @ W_fc  and  a_s = z . W_attn[:64]
__global__ __launch_bounds__(256) void k_proj(const float* __restrict__ h,
                                              const float* __restrict__ Wfc,
                                              const float* __restrict__ Wattn,
                                              int n) {
    __shared__ float sW[IN_DIM * OUTD];   // 32 KB
    __shared__ float sH[16][IN_DIM];      // 8 KB
    __shared__ float sWa[OUTD];
    __shared__ float sRed[8][4];
    int tid = threadIdx.x;
    int j = tid & 63;
    int ty = tid >> 6;
    int lane = tid & 31;
    int wid = tid >> 5;
    int nbase = blockIdx.x * 16;

    for (int i = tid; i < IN_DIM * OUTD / 4; i += 256)
        ((float4*)sW)[i] = ((const float4*)Wfc)[i];
    if (tid < OUTD) sWa[tid] = Wattn[tid];

    for (int i = tid; i < 16 * IN_DIM / 4; i += 256) {
        int nl = i >> 5;
        int kk = i & 31;
        int nn = nbase + nl;
        float4 val = (nn < n) ? ((const float4*)h)[(size_t)nn * 32 + kk]
                              : make_float4(0.f, 0.f, 0.f, 0.f);
        ((float4*)&sH[nl][0])[kk] = val;
    }
    __syncthreads();

    float acc0 = 0.f, acc1 = 0.f, acc2 = 0.f, acc3 = 0.f;
    int nb = ty * 4;
    #pragma unroll 8
    for (int k = 0; k < IN_DIM; k++) {
        float wv = sW[k * OUTD + j];
        acc0 = fmaf(sH[nb + 0][k], wv, acc0);
        acc1 = fmaf(sH[nb + 1][k], wv, acc1);
        acc2 = fmaf(sH[nb + 2][k], wv, acc2);
        acc3 = fmaf(sH[nb + 3][k], wv, acc3);
    }
    int nn = nbase + nb;
    if (nn + 0 < n) g_z[(nn + 0) * OUTD + j] = acc0;
    if (nn + 1 < n) g_z[(nn + 1) * OUTD + j] = acc1;
    if (nn + 2 < n) g_z[(nn + 2) * OUTD + j] = acc2;
    if (nn + 3 < n) g_z[(nn + 3) * OUTD + j] = acc3;

    // a_s reduction: p_i = acc_i * Wa[j], sum over 64 j-threads (2 warps)
    float wa = sWa[j];
    float p0 = acc0 * wa, p1 = acc1 * wa, p2 = acc2 * wa, p3 = acc3 * wa;
    #pragma unroll
    for (int o = 16; o > 0; o >>= 1) {
        p0 += __shfl_xor_sync(0xffffffffu, p0, o);
        p1 += __shfl_xor_sync(0xffffffffu, p1, o);
        p2 += __shfl_xor_sync(0xffffffffu, p2, o);
        p3 += __shfl_xor_sync(0xffffffffu, p3, o);
    }
    if (lane == 0) { sRed[wid][0] = p0; sRed[wid][1] = p1; sRed[wid][2] = p2; sRed[wid][3] = p3; }
    __syncthreads();
    if (tid < 16) {
        int ty2 = tid >> 2, ii = tid & 3;
        int node = nbase + ty2 * 4 + ii;
        if (node < n)
            g_as[node] = sRed[2 * ty2][ii] + sRed[2 * ty2 + 1][ii];
    }
}

// ------------------------------------------------------------------
// K2: in-degree count (4 edges per thread)
__global__ void k_deg(const int* __restrict__ dst, int e) {
    int i4 = (blockIdx.x * blockDim.x + threadIdx.x) * 4;
    if (i4 + 3 < e) {
        int4 d = *(const int4*)(dst + i4);
        atomicAdd(&g_deg[d.x], 1);
        atomicAdd(&g_deg[d.y], 1);
        atomicAdd(&g_deg[d.z], 1);
        atomicAdd(&g_deg[d.w], 1);
    } else {
        for (int i = i4; i < e; i++) atomicAdd(&g_deg[dst[i]], 1);
    }
}

// ------------------------------------------------------------------
// scan (3 kernels)
__global__ __launch_bounds__(SCANB) void k_scan1(int n) {
    __shared__ int wsum[32];
    int b = blockIdx.x, tid = threadIdx.x, lane = tid & 31, wid = tid >> 5;
    int i = b * SCANB + tid;
    int v = (i < n) ? g_deg[i] : 0;
    int x = v;
    #pragma unroll
    for (int o = 1; o < 32; o <<= 1) {
        int t = __shfl_up_sync(0xffffffffu, x, o);
        if (lane >= o) x += t;
    }
    if (lane == 31) wsum[wid] = x;
    __syncthreads();
    if (wid == 0) {
        int s = wsum[lane];
        #pragma unroll
        for (int o = 1; o < 32; o <<= 1) {
            int t = __shfl_up_sync(0xffffffffu, s, o);
            if (lane >= o) s += t;
        }
        wsum[lane] = s;
    }
    __syncthreads();
    int excl = x - v + (wid ? wsum[wid - 1] : 0);
    if (i < n) g_off[i] = excl;
    if (tid == SCANB - 1) g_bsum[b] = excl + v;
}

__global__ __launch_bounds__(128) void k_scan2(int nb, int n) {
    __shared__ int wsum[4];
    int tid = threadIdx.x, lane = tid & 31, wid = tid >> 5;
    int v = (tid < nb) ? g_bsum[tid] : 0;
    int x = v;
    #pragma unroll
    for (int o = 1; o < 32; o <<= 1) {
        int t = __shfl_up_sync(0xffffffffu, x, o);
        if (lane >= o) x += t;
    }
    if (lane == 31) wsum[wid] = x;
    __syncthreads();
    int wofs = 0;
    for (int ww = 0; ww < wid; ww++) wofs += wsum[ww];
    int excl = x - v + wofs;
    if (tid < nb) g_bsum[tid] = excl;
    if (tid == nb - 1) g_off[n] = excl + v;
}

__global__ void k_scan3(int n) {
    int i = blockIdx.x * blockDim.x + threadIdx.x;
    if (i < n) g_off[i] += g_bsum[i >> 10];
}

// ------------------------------------------------------------------
// K3: counting-sort edges by dst; record (src, w=exp(a_s[src]))
__global__ void k_bucket(const int* __restrict__ src, const int* __restrict__ dst, int e) {
    int i = blockIdx.x * blockDim.x + threadIdx.x;
    if (i >= e) return;
    int s = src[i], d = dst[i];
    int pos = g_off[d] + atomicAdd(&g_cur[d], 1);
    float w = __expf(g_as[s]);
    g_ew[pos] = make_int2(s, __float_as_int(w));
}

// ------------------------------------------------------------------
// K4: fused segmented accumulation + output transform.
// out[d] = A/den + B @ W1 + deg * (z[d] @ W2)
//   A = sum w*z[s], B = sum z[s], den = sum w  over incoming edges.
// 64 threads per node (one column each), 4 nodes per block, grid-stride.
__global__ __launch_bounds__(256) void k_accum(const float* __restrict__ Wedge,
                                               float* __restrict__ out,
                                               int n, int ngroups) {
    __shared__ float sW1[OUTD * OUTD];   // W_edge[0:64]   16 KB
    __shared__ float sW2[OUTD * OUTD];   // W_edge[64:128] 16 KB
    __shared__ float sB[4][OUTD];
    __shared__ float sZd[4][OUTD];
    int tid = threadIdx.x;
    int j = tid & 63;
    int ty = tid >> 6;

    for (int i = tid; i < OUTD * OUTD / 4; i += 256) {
        ((float4*)sW1)[i] = ((const float4*)Wedge)[i];
        ((float4*)sW2)[i] = ((const float4*)(Wedge + OUTD * OUTD))[i];
    }
    __syncthreads();

    for (int grp = blockIdx.x; grp < ngroups; grp += gridDim.x) {
        int node = grp * 4 + ty;
        float A = 0.f, B = 0.f, den = 0.f;
        int off0 = 0, off1 = 0;
        float zd = 0.f;
        if (node < n) {
            off0 = g_off[node];
            off1 = g_off[node + 1];
            zd = g_z[(size_t)node * OUTD + j];
            #pragma unroll 4
            for (int e = off0; e < off1; e++) {
                int2 ew = g_ew[e];                    // broadcast
                float w = __int_as_float(ew.y);
                float zv = g_z[(size_t)ew.x * OUTD + j];  // coalesced gather
                A = fmaf(w, zv, A);
                B += zv;
                den += w;
            }
        }
        __syncthreads();   // protect sB/sZd reuse across grid-stride iters
        sB[ty][j] = B;
        sZd[ty][j] = zd;
        __syncthreads();

        float r = (den > 0.f) ? A / den : 0.f;
        float rz = 0.f;
        #pragma unroll 16
        for (int k = 0; k < OUTD; k++) {
            r  = fmaf(sB[ty][k],  sW1[k * OUTD + j], r);
            rz = fmaf(sZd[ty][k], sW2[k * OUTD + j], rz);
        }
        r = fmaf((float)(off1 - off0), rz, r);
        if (node < n) out[(size_t)node * OUTD + j] = r;
    }
}

// ------------------------------------------------------------------
extern "C" void kernel_launch(void* const* d_in, const int* in_sizes, int n_in,
                              void* d_out, int out_size) {
    const float* h      = (const float*)d_in[0];
    const float* W_fc   = (const float*)d_in[1];
    const float* W_attn = (const float*)d_in[2];
    const float* W_edge = (const float*)d_in[3];
    const int*   src    = (const int*)d_in[4];
    const int*   dst    = (const int*)d_in[5];
    float* out = (float*)d_out;

    int n = in_sizes[0] / IN_DIM;   // 100000
    int e = in_sizes[4];            // 1600000
    int nb = (n + SCANB - 1) / SCANB;

    k_init  <<<(n + 255) / 256, 256>>>(n);
    k_proj  <<<(n + 15) / 16, 256>>>(h, W_fc, W_attn, n);
    k_deg   <<<(e / 4 + 255) / 256, 256>>>(dst, e);
    k_scan1 <<<nb, SCANB>>>(n);
    k_scan2 <<<1, 128>>>(nb, n);
    k_scan3 <<<(n + 255) / 256, 256>>>(n);
    k_bucket<<<(e + 255) / 256, 256>>>(src, dst, e);
    int ngroups = (n + 3) / 4;
    k_accum <<<1184, 256>>>(W_edge, out, n, ngroups);
}

// round 4
// speedup vs baseline: 1.8220x; 1.3805x over previous
#include <cuda_runtime.h>
#include <math.h>
#include <stdint.h>

#define IN_DIM 128
#define OUTD   64
#define MAXN   100000
#define MAXE   1600000
#define SCANB  1024

// ---- device scratch ----
__device__ float g_z[MAXN * OUTD];
__device__ float g_as[MAXN];
__device__ int   g_deg[MAXN];
__device__ int   g_off[MAXN + 1];
__device__ int   g_cur[MAXN];
__device__ int2  g_ew[MAXE];
__device__ int   g_bsum[(MAXN + SCANB - 1) / SCANB];

// ------------------------------------------------------------------
__global__ void k_init(int n) {
    int i = blockIdx.x * blockDim.x + threadIdx.x;
    if (i < n) { g_deg[i] = 0; g_cur[i] = 0; }
}

// ------------------------------------------------------------------
// K1: z = h @ W_fc  and  a_s = z . W_attn[:64]
// 64 nodes/block, thread = 4 nodes x 4 cols. Dynamic smem 66560 B.
#define HP 132   // sH row pitch (floats): bank-safe and float4-aligned
__global__ __launch_bounds__(256) void k_proj(const float* __restrict__ h,
                                              const float* __restrict__ Wfc,
                                              const float* __restrict__ Wattn,
                                              int n) {
    extern __shared__ float dyn[];
    float* sW = dyn;              // 128*64 = 8192 floats
    float* sH = dyn + 8192;       // 64 * HP floats
    __shared__ float sWa[OUTD];

    int tid = threadIdx.x;
    int c = tid & 15;             // col group: cols 4c..4c+3
    int r = tid >> 4;             // node group: nodes 4r..4r+3
    int nbase = blockIdx.x * 64;

    if (tid < OUTD) sWa[tid] = Wattn[tid];
    for (int i = tid; i < 2048; i += 256)
        ((float4*)sW)[i] = ((const float4*)Wfc)[i];
    for (int i = tid; i < 2048; i += 256) {
        int nl = i >> 5;          // 32 float4 per 128-float h row
        int kk = i & 31;
        int nn = nbase + nl;
        float4 v = (nn < n) ? ((const float4*)h)[(size_t)nn * 32 + kk]
                            : make_float4(0.f, 0.f, 0.f, 0.f);
        ((float4*)(sH + nl * HP))[kk] = v;
    }
    __syncthreads();

    float4 a0 = {0,0,0,0}, a1 = {0,0,0,0}, a2 = {0,0,0,0}, a3 = {0,0,0,0};
    const float* hb = sH + (4 * r) * HP;
    const float* wb = sW + 4 * c;
    #pragma unroll 4
    for (int k = 0; k < IN_DIM; k++) {
        float4 w = *(const float4*)(wb + k * OUTD);
        float h0 = hb[k], h1 = hb[HP + k], h2 = hb[2 * HP + k], h3 = hb[3 * HP + k];
        a0.x = fmaf(h0, w.x, a0.x); a0.y = fmaf(h0, w.y, a0.y);
        a0.z = fmaf(h0, w.z, a0.z); a0.w = fmaf(h0, w.w, a0.w);
        a1.x = fmaf(h1, w.x, a1.x); a1.y = fmaf(h1, w.y, a1.y);
        a1.z = fmaf(h1, w.z, a1.z); a1.w = fmaf(h1, w.w, a1.w);
        a2.x = fmaf(h2, w.x, a2.x); a2.y = fmaf(h2, w.y, a2.y);
        a2.z = fmaf(h2, w.z, a2.z); a2.w = fmaf(h2, w.w, a2.w);
        a3.x = fmaf(h3, w.x, a3.x); a3.y = fmaf(h3, w.y, a3.y);
        a3.z = fmaf(h3, w.z, a3.z); a3.w = fmaf(h3, w.w, a3.w);
    }

    int node0 = nbase + 4 * r;
    if (node0 + 0 < n) ((float4*)(g_z + (size_t)(node0 + 0) * OUTD))[c] = a0;
    if (node0 + 1 < n) ((float4*)(g_z + (size_t)(node0 + 1) * OUTD))[c] = a1;
    if (node0 + 2 < n) ((float4*)(g_z + (size_t)(node0 + 2) * OUTD))[c] = a2;
    if (node0 + 3 < n) ((float4*)(g_z + (size_t)(node0 + 3) * OUTD))[c] = a3;

    // a_s = z . Wa : partial dot over this thread's 4 cols, reduce over 16 c-lanes
    float4 wa = *(const float4*)(sWa + 4 * c);
    float p0 = fmaf(a0.x, wa.x, fmaf(a0.y, wa.y, fmaf(a0.z, wa.z, a0.w * wa.w)));
    float p1 = fmaf(a1.x, wa.x, fmaf(a1.y, wa.y, fmaf(a1.z, wa.z, a1.w * wa.w)));
    float p2 = fmaf(a2.x, wa.x, fmaf(a2.y, wa.y, fmaf(a2.z, wa.z, a2.w * wa.w)));
    float p3 = fmaf(a3.x, wa.x, fmaf(a3.y, wa.y, fmaf(a3.z, wa.z, a3.w * wa.w)));
    #pragma unroll
    for (int o = 8; o > 0; o >>= 1) {
        p0 += __shfl_xor_sync(0xffffffffu, p0, o);
        p1 += __shfl_xor_sync(0xffffffffu, p1, o);
        p2 += __shfl_xor_sync(0xffffffffu, p2, o);
        p3 += __shfl_xor_sync(0xffffffffu, p3, o);
    }
    if (c == 0) {
        if (node0 + 0 < n) g_as[node0 + 0] = p0;
        if (node0 + 1 < n) g_as[node0 + 1] = p1;
        if (node0 + 2 < n) g_as[node0 + 2] = p2;
        if (node0 + 3 < n) g_as[node0 + 3] = p3;
    }
}

// ------------------------------------------------------------------
__global__ void k_deg(const int* __restrict__ dst, int e) {
    int i4 = (blockIdx.x * blockDim.x + threadIdx.x) * 4;
    if (i4 + 3 < e) {
        int4 d = *(const int4*)(dst + i4);
        atomicAdd(&g_deg[d.x], 1);
        atomicAdd(&g_deg[d.y], 1);
        atomicAdd(&g_deg[d.z], 1);
        atomicAdd(&g_deg[d.w], 1);
    } else {
        for (int i = i4; i < e; i++) atomicAdd(&g_deg[dst[i]], 1);
    }
}

// ------------------------------------------------------------------
__global__ __launch_bounds__(SCANB) void k_scan1(int n) {
    __shared__ int wsum[32];
    int b = blockIdx.x, tid = threadIdx.x, lane = tid & 31, wid = tid >> 5;
    int i = b * SCANB + tid;
    int v = (i < n) ? g_deg[i] : 0;
    int x = v;
    #pragma unroll
    for (int o = 1; o < 32; o <<= 1) {
        int t = __shfl_up_sync(0xffffffffu, x, o);
        if (lane >= o) x += t;
    }
    if (lane == 31) wsum[wid] = x;
    __syncthreads();
    if (wid == 0) {
        int s = wsum[lane];
        #pragma unroll
        for (int o = 1; o < 32; o <<= 1) {
            int t = __shfl_up_sync(0xffffffffu, s, o);
            if (lane >= o) s += t;
        }
        wsum[lane] = s;
    }
    __syncthreads();
    int excl = x - v + (wid ? wsum[wid - 1] : 0);
    if (i < n) g_off[i] = excl;
    if (tid == SCANB - 1) g_bsum[b] = excl + v;
}

__global__ __launch_bounds__(128) void k_scan2(int nb, int n) {
    __shared__ int wsum[4];
    int tid = threadIdx.x, lane = tid & 31, wid = tid >> 5;
    int v = (tid < nb) ? g_bsum[tid] : 0;
    int x = v;
    #pragma unroll
    for (int o = 1; o < 32; o <<= 1) {
        int t = __shfl_up_sync(0xffffffffu, x, o);
        if (lane >= o) x += t;
    }
    if (lane == 31) wsum[wid] = x;
    __syncthreads();
    int wofs = 0;
    for (int ww = 0; ww < wid; ww++) wofs += wsum[ww];
    int excl = x - v + wofs;
    if (tid < nb) g_bsum[tid] = excl;
    if (tid == nb - 1) g_off[n] = excl + v;
}

__global__ void k_scan3(int n) {
    int i = blockIdx.x * blockDim.x + threadIdx.x;
    if (i < n) g_off[i] += g_bsum[i >> 10];
}

// ------------------------------------------------------------------
__global__ void k_bucket(const int* __restrict__ src, const int* __restrict__ dst, int e) {
    int i = blockIdx.x * blockDim.x + threadIdx.x;
    if (i >= e) return;
    int s = src[i], d = dst[i];
    int pos = g_off[d] + atomicAdd(&g_cur[d], 1);
    float w = __expf(g_as[s]);
    g_ew[pos] = make_int2(s, __float_as_int(w));
}

// ------------------------------------------------------------------
// K4: fused segmented accumulation + output transform.
// 16 threads per node (float4 columns), 16 nodes per block.
__global__ __launch_bounds__(256) void k_accum(const float* __restrict__ Wedge,
                                               float* __restrict__ out, int n) {
    __shared__ float sW1[OUTD * OUTD];   // 16 KB
    __shared__ float sW2[OUTD * OUTD];   // 16 KB
    __shared__ float sB[16][68];
    __shared__ float sZ[16][68];
    int tid = threadIdx.x;
    int c = tid & 15;
    int ty = tid >> 4;

    for (int i = tid; i < OUTD * OUTD / 4; i += 256) {
        ((float4*)sW1)[i] = ((const float4*)Wedge)[i];
        ((float4*)sW2)[i] = ((const float4*)(Wedge + OUTD * OUTD))[i];
    }

    int node = blockIdx.x * 16 + ty;
    float4 A = {0,0,0,0}, B = {0,0,0,0}, zd = {0,0,0,0};
    float den = 0.f;
    int off0 = 0, off1 = 0;
    if (node < n) {
        off0 = g_off[node];
        off1 = g_off[node + 1];
        zd = ((const float4*)(g_z + (size_t)node * OUTD))[c];
        int e = off0;
        for (; e + 4 <= off1; e += 4) {
            int2 e0 = g_ew[e], e1 = g_ew[e + 1], e2 = g_ew[e + 2], e3 = g_ew[e + 3];
            float4 z0 = ((const float4*)(g_z + (size_t)e0.x * OUTD))[c];
            float4 z1 = ((const float4*)(g_z + (size_t)e1.x * OUTD))[c];
            float4 z2 = ((const float4*)(g_z + (size_t)e2.x * OUTD))[c];
            float4 z3 = ((const float4*)(g_z + (size_t)e3.x * OUTD))[c];
            float w0 = __int_as_float(e0.y), w1 = __int_as_float(e1.y);
            float w2 = __int_as_float(e2.y), w3 = __int_as_float(e3.y);
            A.x = fmaf(w0, z0.x, A.x); A.y = fmaf(w0, z0.y, A.y);
            A.z = fmaf(w0, z0.z, A.z); A.w = fmaf(w0, z0.w, A.w);
            A.x = fmaf(w1, z1.x, A.x); A.y = fmaf(w1, z1.y, A.y);
            A.z = fmaf(w1, z1.z, A.z); A.w = fmaf(w1, z1.w, A.w);
            A.x = fmaf(w2, z2.x, A.x); A.y = fmaf(w2, z2.y, A.y);
            A.z = fmaf(w2, z2.z, A.z); A.w = fmaf(w2, z2.w, A.w);
            A.x = fmaf(w3, z3.x, A.x); A.y = fmaf(w3, z3.y, A.y);
            A.z = fmaf(w3, z3.z, A.z); A.w = fmaf(w3, z3.w, A.w);
            B.x += (z0.x + z1.x) + (z2.x + z3.x);
            B.y += (z0.y + z1.y) + (z2.y + z3.y);
            B.z += (z0.z + z1.z) + (z2.z + z3.z);
            B.w += (z0.w + z1.w) + (z2.w + z3.w);
            den += (w0 + w1) + (w2 + w3);
        }
        for (; e < off1; e++) {
            int2 ew = g_ew[e];
            float w = __int_as_float(ew.y);
            float4 zv = ((const float4*)(g_z + (size_t)ew.x * OUTD))[c];
            A.x = fmaf(w, zv.x, A.x); A.y = fmaf(w, zv.y, A.y);
            A.z = fmaf(w, zv.z, A.z); A.w = fmaf(w, zv.w, A.w);
            B.x += zv.x; B.y += zv.y; B.z += zv.z; B.w += zv.w;
            den += w;
        }
    }
    *(float4*)&sB[ty][4 * c] = B;
    *(float4*)&sZ[ty][4 * c] = zd;
    __syncthreads();

    float invden = (den > 0.f) ? 1.0f / den : 0.f;
    float4 r; r.x = A.x * invden; r.y = A.y * invden;
    r.z = A.z * invden; r.w = A.w * invden;
    float4 rz = {0,0,0,0};
    const float* w1p = sW1 + 4 * c;
    const float* w2p = sW2 + 4 * c;
    #pragma unroll 4
    for (int k = 0; k < OUTD; k++) {
        float bk = sB[ty][k], zk = sZ[ty][k];
        float4 w1 = *(const float4*)(w1p + k * OUTD);
        float4 w2 = *(const float4*)(w2p + k * OUTD);
        r.x = fmaf(bk, w1.x, r.x); r.y = fmaf(bk, w1.y, r.y);
        r.z = fmaf(bk, w1.z, r.z); r.w = fmaf(bk, w1.w, r.w);
        rz.x = fmaf(zk, w2.x, rz.x); rz.y = fmaf(zk, w2.y, rz.y);
        rz.z = fmaf(zk, w2.z, rz.z); rz.w = fmaf(zk, w2.w, rz.w);
    }
    float degf = (float)(off1 - off0);
    r.x = fmaf(degf, rz.x, r.x); r.y = fmaf(degf, rz.y, r.y);
    r.z = fmaf(degf, rz.z, r.z); r.w = fmaf(degf, rz.w, r.w);
    if (node < n) ((float4*)(out + (size_t)node * OUTD))[c] = r;
}

// ------------------------------------------------------------------
extern "C" void kernel_launch(void* const* d_in, const int* in_sizes, int n_in,
                              void* d_out, int out_size) {
    const float* h      = (const float*)d_in[0];
    const float* W_fc   = (const float*)d_in[1];
    const float* W_attn = (const float*)d_in[2];
    const float* W_edge = (const float*)d_in[3];
    const int*   src    = (const int*)d_in[4];
    const int*   dst    = (const int*)d_in[5];
    float* out = (float*)d_out;

    int n = in_sizes[0] / IN_DIM;   // 100000
    int e = in_sizes[4];            // 1600000
    int nb = (n + SCANB - 1) / SCANB;
    const int PROJ_SMEM = (8192 + 64 * HP) * 4;   // 66560 bytes

    cudaFuncSetAttribute(k_proj, cudaFuncAttributeMaxDynamicSharedMemorySize, PROJ_SMEM);

    k_init  <<<(n + 255) / 256, 256>>>(n);
    k_proj  <<<(n + 63) / 64, 256, PROJ_SMEM>>>(h, W_fc, W_attn, n);
    k_deg   <<<(e / 4 + 255) / 256, 256>>>(dst, e);
    k_scan1 <<<nb, SCANB>>>(n);
    k_scan2 <<<1, 128>>>(nb, n);
    k_scan3 <<<(n + 255) / 256, 256>>>(n);
    k_bucket<<<(e + 255) / 256, 256>>>(src, dst, e);
    k_accum <<<(n + 15) / 16, 256>>>(W_edge, out, n);
}

// round 5
// speedup vs baseline: 2.2217x; 1.2194x over previous
#include <cuda_runtime.h>
#include <math.h>
#include <stdint.h>

#define IN_DIM 128
#define OUTD   64
#define MAXN   100000
#define MAXE   1600000
#define SCANB  1024
#define HP 132   // proj sH pitch (floats)
#define PP 68    // post sB/sZ pitch (floats)

typedef unsigned long long u64;

// ---- packed f32x2 helpers (sm_103a FFMA2 path) ----
__device__ __forceinline__ u64 f2_fma(u64 a, u64 b, u64 c) {
    u64 d; asm("fma.rn.f32x2 %0, %1, %2, %3;" : "=l"(d) : "l"(a), "l"(b), "l"(c)); return d;
}
__device__ __forceinline__ u64 f2_add(u64 a, u64 b) {
    u64 d; asm("add.rn.f32x2 %0, %1, %2;" : "=l"(d) : "l"(a), "l"(b)); return d;
}
__device__ __forceinline__ u64 f2_pack(float x) {
    u64 d; asm("mov.b64 %0, {%1, %1};" : "=l"(d) : "f"(x)); return d;
}
__device__ __forceinline__ u64 f2_pack2(float x, float y) {
    u64 d; asm("mov.b64 %0, {%1, %2};" : "=l"(d) : "f"(x), "f"(y)); return d;
}
__device__ __forceinline__ float2 f2_unpack(u64 a) {
    float lo, hi; asm("mov.b64 {%0, %1}, %2;" : "=f"(lo), "=f"(hi) : "l"(a));
    return make_float2(lo, hi);
}

// ---- device scratch ----
__device__ float g_z[MAXN * OUTD];
__device__ float g_B[MAXN * OUTD];
__device__ float g_as[MAXN];
__device__ int   g_deg[MAXN];
__device__ int   g_off[MAXN + 1];
__device__ int   g_cur[MAXN];
__device__ int2  g_ew[MAXE];
__device__ int   g_bsum[(MAXN + SCANB - 1) / SCANB];

// ------------------------------------------------------------------
__global__ void k_init(int n) {
    int i = blockIdx.x * blockDim.x + threadIdx.x;
    if (i < n) { g_deg[i] = 0; g_cur[i] = 0; }
}

// ------------------------------------------------------------------
// K1: z = h @ W_fc  and  a_s = z . W_attn[:64]
// 64 nodes/block, thread = 4 nodes x 4 cols, FFMA2 inner loop.
__global__ __launch_bounds__(256) void k_proj(const float* __restrict__ h,
                                              const float* __restrict__ Wfc,
                                              const float* __restrict__ Wattn,
                                              int n) {
    extern __shared__ float dyn[];
    float* sW = dyn;              // 8192 floats
    float* sH = dyn + 8192;       // 64 * HP floats
    __shared__ float sWa[OUTD];

    int tid = threadIdx.x;
    int c = tid & 15;
    int r = tid >> 4;
    int nbase = blockIdx.x * 64;

    if (tid < OUTD) sWa[tid] = Wattn[tid];
    for (int i = tid; i < 2048; i += 256)
        ((float4*)sW)[i] = ((const float4*)Wfc)[i];
    for (int i = tid; i < 2048; i += 256) {
        int nl = i >> 5;
        int kk = i & 31;
        int nn = nbase + nl;
        float4 v = (nn < n) ? ((const float4*)h)[(size_t)nn * 32 + kk]
                            : make_float4(0.f, 0.f, 0.f, 0.f);
        ((float4*)(sH + nl * HP))[kk] = v;
    }
    __syncthreads();

    u64 acc[4][2];
    #pragma unroll
    for (int i = 0; i < 4; i++) { acc[i][0] = 0ull; acc[i][1] = 0ull; }
    const float* hb = sH + (4 * r) * HP;
    const float* wb = sW + 4 * c;

    #pragma unroll 4
    for (int k4 = 0; k4 < IN_DIM; k4 += 4) {
        float4 hv[4];
        #pragma unroll
        for (int i = 0; i < 4; i++)
            hv[i] = *(const float4*)(hb + i * HP + k4);
        #pragma unroll
        for (int kk = 0; kk < 4; kk++) {
            ulonglong2 w2 = *(const ulonglong2*)(wb + (k4 + kk) * OUTD);
            #pragma unroll
            for (int i = 0; i < 4; i++) {
                u64 hp = f2_pack(((const float*)&hv[i])[kk]);
                acc[i][0] = f2_fma(hp, w2.x, acc[i][0]);
                acc[i][1] = f2_fma(hp, w2.y, acc[i][1]);
            }
        }
    }

    int node0 = nbase + 4 * r;
    float4 ov[4];
    #pragma unroll
    for (int i = 0; i < 4; i++) {
        float2 lo = f2_unpack(acc[i][0]);
        float2 hi = f2_unpack(acc[i][1]);
        ov[i] = make_float4(lo.x, lo.y, hi.x, hi.y);
        if (node0 + i < n)
            ((float4*)(g_z + (size_t)(node0 + i) * OUTD))[c] = ov[i];
    }

    float4 wa = *(const float4*)(sWa + 4 * c);
    float p[4];
    #pragma unroll
    for (int i = 0; i < 4; i++)
        p[i] = fmaf(ov[i].x, wa.x, fmaf(ov[i].y, wa.y, fmaf(ov[i].z, wa.z, ov[i].w * wa.w)));
    #pragma unroll
    for (int o = 8; o > 0; o >>= 1) {
        p[0] += __shfl_xor_sync(0xffffffffu, p[0], o);
        p[1] += __shfl_xor_sync(0xffffffffu, p[1], o);
        p[2] += __shfl_xor_sync(0xffffffffu, p[2], o);
        p[3] += __shfl_xor_sync(0xffffffffu, p[3], o);
    }
    if (c == 0) {
        #pragma unroll
        for (int i = 0; i < 4; i++)
            if (node0 + i < n) g_as[node0 + i] = p[i];
    }
}

// ------------------------------------------------------------------
__global__ void k_deg(const int* __restrict__ dst, int e) {
    int i4 = (blockIdx.x * blockDim.x + threadIdx.x) * 4;
    if (i4 + 3 < e) {
        int4 d = *(const int4*)(dst + i4);
        atomicAdd(&g_deg[d.x], 1);
        atomicAdd(&g_deg[d.y], 1);
        atomicAdd(&g_deg[d.z], 1);
        atomicAdd(&g_deg[d.w], 1);
    } else {
        for (int i = i4; i < e; i++) atomicAdd(&g_deg[dst[i]], 1);
    }
}

// ------------------------------------------------------------------
__global__ __launch_bounds__(SCANB) void k_scan1(int n) {
    __shared__ int wsum[32];
    int b = blockIdx.x, tid = threadIdx.x, lane = tid & 31, wid = tid >> 5;
    int i = b * SCANB + tid;
    int v = (i < n) ? g_deg[i] : 0;
    int x = v;
    #pragma unroll
    for (int o = 1; o < 32; o <<= 1) {
        int t = __shfl_up_sync(0xffffffffu, x, o);
        if (lane >= o) x += t;
    }
    if (lane == 31) wsum[wid] = x;
    __syncthreads();
    if (wid == 0) {
        int s = wsum[lane];
        #pragma unroll
        for (int o = 1; o < 32; o <<= 1) {
            int t = __shfl_up_sync(0xffffffffu, s, o);
            if (lane >= o) s += t;
        }
        wsum[lane] = s;
    }
    __syncthreads();
    int excl = x - v + (wid ? wsum[wid - 1] : 0);
    if (i < n) g_off[i] = excl;
    if (tid == SCANB - 1) g_bsum[b] = excl + v;
}

__global__ __launch_bounds__(128) void k_scan2(int nb, int n) {
    __shared__ int wsum[4];
    int tid = threadIdx.x, lane = tid & 31, wid = tid >> 5;
    int v = (tid < nb) ? g_bsum[tid] : 0;
    int x = v;
    #pragma unroll
    for (int o = 1; o < 32; o <<= 1) {
        int t = __shfl_up_sync(0xffffffffu, x, o);
        if (lane >= o) x += t;
    }
    if (lane == 31) wsum[wid] = x;
    __syncthreads();
    int wofs = 0;
    for (int ww = 0; ww < wid; ww++) wofs += wsum[ww];
    int excl = x - v + wofs;
    if (tid < nb) g_bsum[tid] = excl;
    if (tid == nb - 1) g_off[n] = excl + v;
}

__global__ void k_scan3(int n) {
    int i = blockIdx.x * blockDim.x + threadIdx.x;
    if (i < n) g_off[i] += g_bsum[i >> 10];
}

// ------------------------------------------------------------------
__global__ void k_bucket(const int* __restrict__ src, const int* __restrict__ dst, int e) {
    int i = blockIdx.x * blockDim.x + threadIdx.x;
    if (i >= e) return;
    int s = src[i], d = dst[i];
    int pos = g_off[d] + atomicAdd(&g_cur[d], 1);
    float w = __expf(g_as[s]);
    g_ew[pos] = make_int2(s, __float_as_int(w));
}

// ------------------------------------------------------------------
// K4: gather/reduce only. 16 threads/node (float4 cols), no smem, no sync.
// Writes out = A/den, g_B = B.
__global__ __launch_bounds__(256) void k_accum(float* __restrict__ out, int n) {
    int tid = threadIdx.x;
    int c = tid & 15;
    int ty = tid >> 4;
    int node = blockIdx.x * 16 + ty;
    if (node >= n) return;

    int off0 = g_off[node], off1 = g_off[node + 1];
    u64 A0 = 0, A1 = 0, B0 = 0, B1 = 0;
    float den = 0.f;

    int e = off0;
    for (; e + 4 <= off1; e += 4) {
        int2 e0 = g_ew[e], e1 = g_ew[e + 1], e2 = g_ew[e + 2], e3 = g_ew[e + 3];
        ulonglong2 z0 = ((const ulonglong2*)(g_z + (size_t)e0.x * OUTD))[c];
        ulonglong2 z1 = ((const ulonglong2*)(g_z + (size_t)e1.x * OUTD))[c];
        ulonglong2 z2 = ((const ulonglong2*)(g_z + (size_t)e2.x * OUTD))[c];
        ulonglong2 z3 = ((const ulonglong2*)(g_z + (size_t)e3.x * OUTD))[c];
        float w0 = __int_as_float(e0.y), w1 = __int_as_float(e1.y);
        float w2 = __int_as_float(e2.y), w3 = __int_as_float(e3.y);
        u64 p0 = f2_pack(w0), p1 = f2_pack(w1), p2 = f2_pack(w2), p3 = f2_pack(w3);
        A0 = f2_fma(p0, z0.x, A0); A1 = f2_fma(p0, z0.y, A1);
        A0 = f2_fma(p1, z1.x, A0); A1 = f2_fma(p1, z1.y, A1);
        A0 = f2_fma(p2, z2.x, A0); A1 = f2_fma(p2, z2.y, A1);
        A0 = f2_fma(p3, z3.x, A0); A1 = f2_fma(p3, z3.y, A1);
        B0 = f2_add(B0, z0.x); B1 = f2_add(B1, z0.y);
        B0 = f2_add(B0, z1.x); B1 = f2_add(B1, z1.y);
        B0 = f2_add(B0, z2.x); B1 = f2_add(B1, z2.y);
        B0 = f2_add(B0, z3.x); B1 = f2_add(B1, z3.y);
        den += (w0 + w1) + (w2 + w3);
    }
    for (; e < off1; e++) {
        int2 ew = g_ew[e];
        float w = __int_as_float(ew.y);
        ulonglong2 zv = ((const ulonglong2*)(g_z + (size_t)ew.x * OUTD))[c];
        u64 wp = f2_pack(w);
        A0 = f2_fma(wp, zv.x, A0); A1 = f2_fma(wp, zv.y, A1);
        B0 = f2_add(B0, zv.x); B1 = f2_add(B1, zv.y);
        den += w;
    }

    float invden = (den > 0.f) ? 1.0f / den : 0.f;
    float2 a0 = f2_unpack(A0), a1 = f2_unpack(A1);
    float2 b0 = f2_unpack(B0), b1 = f2_unpack(B1);
    float4 ra = make_float4(a0.x * invden, a0.y * invden, a1.x * invden, a1.y * invden);
    float4 rb = make_float4(b0.x, b0.y, b1.x, b1.y);
    ((float4*)(out + (size_t)node * OUTD))[c] = ra;
    ((float4*)(g_B + (size_t)node * OUTD))[c] = rb;
}

// ------------------------------------------------------------------
// K5: out += B @ W1 + deg * (z @ W2). 64 nodes/block, thread = 4 nodes x 4 cols.
__global__ __launch_bounds__(256) void k_post(const float* __restrict__ Wedge,
                                              float* __restrict__ out, int n) {
    extern __shared__ float dyn2[];
    float* sW1 = dyn2;             // 4096
    float* sW2 = dyn2 + 4096;      // 4096
    float* sB  = dyn2 + 8192;      // 64 * PP
    float* sZ  = sB + 64 * PP;     // 64 * PP
    __shared__ float sDeg[64];

    int tid = threadIdx.x;
    int c = tid & 15;
    int r = tid >> 4;
    int nbase = blockIdx.x * 64;

    for (int i = tid; i < 1024; i += 256) {
        ((float4*)sW1)[i] = ((const float4*)Wedge)[i];
        ((float4*)sW2)[i] = ((const float4*)(Wedge + OUTD * OUTD))[i];
    }
    for (int i = tid; i < 1024; i += 256) {
        int nl = i >> 4;
        int kk = i & 15;
        int nn = nbase + nl;
        float4 bv = make_float4(0.f, 0.f, 0.f, 0.f);
        float4 zv = bv;
        if (nn < n) {
            bv = ((const float4*)(g_B + (size_t)nn * OUTD))[kk];
            zv = ((const float4*)(g_z + (size_t)nn * OUTD))[kk];
        }
        ((float4*)(sB + nl * PP))[kk] = bv;
        ((float4*)(sZ + nl * PP))[kk] = zv;
    }
    if (tid < 64) {
        int nn = nbase + tid;
        sDeg[tid] = (nn < n) ? (float)(g_off[nn + 1] - g_off[nn]) : 0.f;
    }
    __syncthreads();

    u64 rB[4][2], rZ[4][2];
    #pragma unroll
    for (int i = 0; i < 4; i++) { rB[i][0] = rB[i][1] = 0ull; rZ[i][0] = rZ[i][1] = 0ull; }
    const float* bb  = sB + (4 * r) * PP;
    const float* zb  = sZ + (4 * r) * PP;
    const float* w1b = sW1 + 4 * c;
    const float* w2b = sW2 + 4 * c;

    #pragma unroll 4
    for (int k4 = 0; k4 < OUTD; k4 += 4) {
        float4 bv[4], zv[4];
        #pragma unroll
        for (int i = 0; i < 4; i++) {
            bv[i] = *(const float4*)(bb + i * PP + k4);
            zv[i] = *(const float4*)(zb + i * PP + k4);
        }
        #pragma unroll
        for (int kk = 0; kk < 4; kk++) {
            ulonglong2 w1 = *(const ulonglong2*)(w1b + (k4 + kk) * OUTD);
            ulonglong2 w2 = *(const ulonglong2*)(w2b + (k4 + kk) * OUTD);
            #pragma unroll
            for (int i = 0; i < 4; i++) {
                u64 bp = f2_pack(((const float*)&bv[i])[kk]);
                u64 zp = f2_pack(((const float*)&zv[i])[kk]);
                rB[i][0] = f2_fma(bp, w1.x, rB[i][0]);
                rB[i][1] = f2_fma(bp, w1.y, rB[i][1]);
                rZ[i][0] = f2_fma(zp, w2.x, rZ[i][0]);
                rZ[i][1] = f2_fma(zp, w2.y, rZ[i][1]);
            }
        }
    }

    #pragma unroll
    for (int i = 0; i < 4; i++) {
        int nn = nbase + 4 * r + i;
        if (nn < n) {
            float4 o = ((const float4*)(out + (size_t)nn * OUTD))[c];
            float dg = sDeg[4 * r + i];
            float2 b0 = f2_unpack(rB[i][0]), b1 = f2_unpack(rB[i][1]);
            float2 z0 = f2_unpack(rZ[i][0]), z1 = f2_unpack(rZ[i][1]);
            o.x += b0.x + dg * z0.x;
            o.y += b0.y + dg * z0.y;
            o.z += b1.x + dg * z1.x;
            o.w += b1.y + dg * z1.y;
            ((float4*)(out + (size_t)nn * OUTD))[c] = o;
        }
    }
}

// ------------------------------------------------------------------
extern "C" void kernel_launch(void* const* d_in, const int* in_sizes, int n_in,
                              void* d_out, int out_size) {
    const float* h      = (const float*)d_in[0];
    const float* W_fc   = (const float*)d_in[1];
    const float* W_attn = (const float*)d_in[2];
    const float* W_edge = (const float*)d_in[3];
    const int*   src    = (const int*)d_in[4];
    const int*   dst    = (const int*)d_in[5];
    float* out = (float*)d_out;

    int n = in_sizes[0] / IN_DIM;   // 100000
    int e = in_sizes[4];            // 1600000
    int nb = (n + SCANB - 1) / SCANB;
    const int PROJ_SMEM = (8192 + 64 * HP) * 4;       // 66560 B
    const int POST_SMEM = (8192 + 2 * 64 * PP) * 4;   // 67584 B

    cudaFuncSetAttribute(k_proj, cudaFuncAttributeMaxDynamicSharedMemorySize, PROJ_SMEM);
    cudaFuncSetAttribute(k_post, cudaFuncAttributeMaxDynamicSharedMemorySize, POST_SMEM);

    k_init  <<<(n + 255) / 256, 256>>>(n);
    k_proj  <<<(n + 63) / 64, 256, PROJ_SMEM>>>(h, W_fc, W_attn, n);
    k_deg   <<<(e / 4 + 255) / 256, 256>>>(dst, e);
    k_scan1 <<<nb, SCANB>>>(n);
    k_scan2 <<<1, 128>>>(nb, n);
    k_scan3 <<<(n + 255) / 256, 256>>>(n);
    k_bucket<<<(e + 255) / 256, 256>>>(src, dst, e);
    k_accum <<<(n + 15) / 16, 256>>>(out, n);
    k_post  <<<(n + 63) / 64, 256, POST_SMEM>>>(W_edge, out, n);
}